// round 1
// baseline (speedup 1.0000x reference)
#include <cuda_runtime.h>

// LSTM: B=128, T=256, H=1024, C=10
// Persistent-grid fp32 kernel using packed fma.rn.f32x2 (Blackwell dual-fp32).
// 128 CTAs (1/SM, all co-resident), weights SMEM-resident, software grid
// barrier per timestep, h ping-pong in __device__ global memory.

#define BB   128
#define TT   256
#define HH   1024
#define CC   10
#define NCTA 128
#define NTHR 256
#define JPC  8        // hidden units per CTA
#define KC   64       // K chunk staged per iteration

typedef unsigned long long ull;

// SMEM layout (bytes):
//   s_w   : HH*32*4      = 131072   (weights, [k][r], r = gate*8+jj)
//   s_h2  : KC*BB*8      = 65536    (h chunk, f32x2-duplicated, [kk][b])
//   s_z   : 32*BB*4      = 16384    (gate pre-activations, [r][b])
//   s_c   : BB*JPC*4     = 4096     (cell state)
//   s_xw  : 32*4, s_b : 32*4 = 256
#define SMEM_W   0
#define SMEM_H2  (131072)
#define SMEM_Z   (131072 + 65536)
#define SMEM_C   (131072 + 65536 + 16384)
#define SMEM_XW  (131072 + 65536 + 16384 + 4096)
#define SMEM_BIA (SMEM_XW + 128)
#define SMEM_TOTAL (SMEM_BIA + 128)

__device__ float    g_h[2][HH * BB];   // h ping-pong, layout [k][b]
__device__ unsigned g_bar;             // monotonic barrier counter

__global__ void reset_kernel() { g_bar = 0u; }

__device__ __forceinline__ ull dup2(float v) {
    ull r; asm("mov.b64 %0, {%1, %1};" : "=l"(r) : "f"(v)); return r;
}
__device__ __forceinline__ ull pk2(float lo, float hi) {
    ull r; asm("mov.b64 %0, {%1, %2};" : "=l"(r) : "f"(lo), "f"(hi)); return r;
}
__device__ __forceinline__ void fma2(ull& d, ull a, ull b) {
    asm("fma.rn.f32x2 %0, %1, %2, %0;" : "+l"(d) : "l"(a), "l"(b));
}
__device__ __forceinline__ void up2(float& lo, float& hi, ull v) {
    asm("mov.b64 {%0, %1}, %2;" : "=f"(lo), "=f"(hi) : "l"(v));
}
__device__ __forceinline__ float sigf(float z) {
    return 1.0f / (1.0f + __expf(-z));
}

__global__ void __launch_bounds__(NTHR, 1) lstm_kernel(
    const float* __restrict__ x,
    const float* __restrict__ Wgx, const float* __restrict__ Wgh, const float* __restrict__ bg,
    const float* __restrict__ Wix, const float* __restrict__ Wih, const float* __restrict__ bi,
    const float* __restrict__ Wfx, const float* __restrict__ Wfh, const float* __restrict__ bf,
    const float* __restrict__ Wox, const float* __restrict__ Woh, const float* __restrict__ bo)
{
    extern __shared__ char smem[];
    float* s_w    = (float*)(smem + SMEM_W);
    ull*   s_h2   = (ull*)  (smem + SMEM_H2);
    float* s_z    = (float*)(smem + SMEM_Z);
    float* s_c    = (float*)(smem + SMEM_C);
    float* s_xw   = (float*)(smem + SMEM_XW);
    float* s_bias = (float*)(smem + SMEM_BIA);

    const int tid    = threadIdx.x;
    const int cta    = blockIdx.x;
    const int j_base = cta * JPC;

    // ---- one-time init: transpose weight slice into SMEM [k][r] ----
    const float* Wh[4] = {Wgh, Wih, Wfh, Woh};
#pragma unroll
    for (int g = 0; g < 4; ++g) {
        const float* Wsrc = Wh[g] + (size_t)j_base * HH;
        for (int idx = tid; idx < JPC * HH; idx += NTHR) {
            int jj = idx >> 10;
            int k  = idx & (HH - 1);
            s_w[k * 32 + g * 8 + jj] = Wsrc[jj * HH + k];
        }
    }
    if (tid < 8) {
        s_xw[0  + tid] = Wgx[j_base + tid];
        s_xw[8  + tid] = Wix[j_base + tid];
        s_xw[16 + tid] = Wfx[j_base + tid];
        s_xw[24 + tid] = Wox[j_base + tid];
        s_bias[0  + tid] = bg[j_base + tid];
        s_bias[8  + tid] = bi[j_base + tid];
        s_bias[16 + tid] = bf[j_base + tid];
        s_bias[24 + tid] = bo[j_base + tid];
    }
    for (int i = tid; i < BB * JPC; i += NTHR) s_c[i] = 0.0f;
    __syncthreads();

    // GEMM thread mapping: 8 threads across r (4 rows each, as 2 f32x2 pairs),
    // 32 threads across b (4 batch each).
    const int r0  = (tid & 7) * 4;
    const int b0  = (tid >> 3) * 4;
    // elementwise mapping: one b per thread-pair, 4 hidden units each
    const int eb  = tid >> 1;
    const int ej0 = (tid & 1) * 4;

    for (int t = 0; t < TT; ++t) {
        ull acc[4][2];
#pragma unroll
        for (int i = 0; i < 4; ++i) { acc[i][0] = 0ull; acc[i][1] = 0ull; }

        if (t > 0) {
            const float* hprev = g_h[(t - 1) & 1];
            for (int ch = 0; ch < HH / KC; ++ch) {
                __syncthreads();
                // stage h chunk [KC][BB] -> duplicated f32x2 in SMEM
                const float4* src = (const float4*)(hprev + ch * (KC * BB));
#pragma unroll
                for (int q = 0; q < (KC * BB / 4) / NTHR; ++q) {
                    float4 v = src[q * NTHR + tid];
                    ull* dst = s_h2 + (size_t)(q * NTHR + tid) * 4;
                    dst[0] = dup2(v.x); dst[1] = dup2(v.y);
                    dst[2] = dup2(v.z); dst[3] = dup2(v.w);
                }
                __syncthreads();
                const float* wp = s_w + ch * KC * 32 + r0;
#pragma unroll 8
                for (int kk = 0; kk < KC; ++kk) {
                    float4 wv = *(const float4*)(wp + kk * 32);
                    ull w01 = pk2(wv.x, wv.y);
                    ull w23 = pk2(wv.z, wv.w);
                    const ull* hp = s_h2 + kk * BB + b0;
                    ull h0 = hp[0], h1 = hp[1], h2 = hp[2], h3 = hp[3];
                    fma2(acc[0][0], h0, w01); fma2(acc[0][1], h0, w23);
                    fma2(acc[1][0], h1, w01); fma2(acc[1][1], h1, w23);
                    fma2(acc[2][0], h2, w01); fma2(acc[2][1], h2, w23);
                    fma2(acc[3][0], h3, w01); fma2(acc[3][1], h3, w23);
                }
            }
        }

        // scatter accumulators to s_z[r][b]
#pragma unroll
        for (int ib = 0; ib < 4; ++ib) {
            float lo, hi;
            up2(lo, hi, acc[ib][0]);
            s_z[(r0 + 0) * BB + b0 + ib] = lo;
            s_z[(r0 + 1) * BB + b0 + ib] = hi;
            up2(lo, hi, acc[ib][1]);
            s_z[(r0 + 2) * BB + b0 + ib] = lo;
            s_z[(r0 + 3) * BB + b0 + ib] = hi;
        }
        __syncthreads();

        // elementwise LSTM cell update for 4 (b, jj) pairs
        float* hcur = g_h[t & 1];
        const float xv = x[eb * TT + t];
#pragma unroll
        for (int m = 0; m < 4; ++m) {
            int jj = ej0 + m;
            float zg = s_z[(jj)      * BB + eb] + xv * s_xw[jj]      + s_bias[jj];
            float zi = s_z[(8  + jj) * BB + eb] + xv * s_xw[8  + jj] + s_bias[8  + jj];
            float zf = s_z[(16 + jj) * BB + eb] + xv * s_xw[16 + jj] + s_bias[16 + jj];
            float zo = s_z[(24 + jj) * BB + eb] + xv * s_xw[24 + jj] + s_bias[24 + jj];
            float gg = tanhf(zg);
            float ii = sigf(zi);
            float ff = sigf(zf);
            float oo = sigf(zo);
            float c  = s_c[eb * JPC + jj];
            c = gg * ii + c * ff;
            s_c[eb * JPC + jj] = c;
            hcur[(j_base + jj) * BB + eb] = tanhf(c) * oo;
        }

        // ---- grid barrier (monotonic counter, reset per launch) ----
        __syncthreads();
        if (tid == 0) {
            __threadfence();
            atomicAdd(&g_bar, 1u);
            const unsigned target = (unsigned)(t + 1) * NCTA;
            while (*(volatile unsigned*)&g_bar < target) { __nanosleep(64); }
            __threadfence();
        }
        __syncthreads();
    }
}

__global__ void proj_kernel(const float* __restrict__ Wp,
                            const float* __restrict__ bp,
                            float* __restrict__ out)
{
    __shared__ float red[NTHR][CC];
    const int b   = blockIdx.x;
    const int tid = threadIdx.x;
    const float* hf = g_h[(TT - 1) & 1];

    float p[CC];
#pragma unroll
    for (int c = 0; c < CC; ++c) p[c] = 0.0f;
    for (int k = tid; k < HH; k += NTHR) {
        float hv = hf[k * BB + b];
#pragma unroll
        for (int c = 0; c < CC; ++c) p[c] += hv * Wp[k * CC + c];
    }
#pragma unroll
    for (int c = 0; c < CC; ++c) red[tid][c] = p[c];
    __syncthreads();
    if (tid < CC) {
        float s = 0.0f;
        for (int i = 0; i < NTHR; ++i) s += red[i][tid];
        out[b * CC + tid] = s + bp[tid];
    }
}

extern "C" void kernel_launch(void* const* d_in, const int* in_sizes, int n_in,
                              void* d_out, int out_size)
{
    (void)in_sizes; (void)n_in; (void)out_size;
    const float* x   = (const float*)d_in[0];
    const float* Wgx = (const float*)d_in[1];
    const float* Wgh = (const float*)d_in[2];
    const float* bg  = (const float*)d_in[3];
    const float* Wix = (const float*)d_in[4];
    const float* Wih = (const float*)d_in[5];
    const float* bi  = (const float*)d_in[6];
    const float* Wfx = (const float*)d_in[7];
    const float* Wfh = (const float*)d_in[8];
    const float* bf  = (const float*)d_in[9];
    const float* Wox = (const float*)d_in[10];
    const float* Woh = (const float*)d_in[11];
    const float* bo  = (const float*)d_in[12];
    const float* Wp  = (const float*)d_in[13];
    const float* bp  = (const float*)d_in[14];

    cudaFuncSetAttribute(lstm_kernel,
                         cudaFuncAttributeMaxDynamicSharedMemorySize, SMEM_TOTAL);

    reset_kernel<<<1, 1>>>();
    lstm_kernel<<<NCTA, NTHR, SMEM_TOTAL>>>(x, Wgx, Wgh, bg, Wix, Wih, bi,
                                            Wfx, Wfh, bf, Wox, Woh, bo);
    proj_kernel<<<BB, NTHR>>>(Wp, bp, (float*)d_out);
}

// round 3
// speedup vs baseline: 2.5272x; 2.5272x over previous
#include <cuda_runtime.h>
#include <cuda_bf16.h>
#include <stdint.h>

// LSTM B=128,T=256,H=1024,C=10 — persistent mma.sync(bf16, 3-pass split) kernel.
// sm_80-class PTX only (mma.sync / ldmatrix / cp.async) — compiles for compute_103.

#define BB   128
#define TT   256
#define HH   1024
#define CC   10
#define NCTA 128
#define NTHR 128
#define JPC  8          // hidden units per CTA (32 gate rows)
#define KC   64         // K per staged chunk
#define NCH  16         // chunks per step

// ---- SMEM layout (byte offsets from 128B-aligned base) ----
// W planes: var(hi/lo) x 64 ktiles x (32 n-rows x 32B)  = 2*65536 = 131072
#define W_VAR   65536
#define A_BASE  131072
#define A_KT    4128          // 128*32 + 32 skew
#define A_VARS  16512         // 4 ktiles
#define A_BUF   33024         // 2 vars
#define MISC    (A_BASE + 2*A_BUF)      // 197120
#define SM_XW   (MISC)
#define SM_BS   (MISC + 128)
#define SMEM_DYN (MISC + 256 + 128)

typedef unsigned short ushort_t;

__device__ __align__(16) __nv_bfloat16 g_hhi[2][BB * HH];  // [b][k]
__device__ __align__(16) __nv_bfloat16 g_hlo[2][BB * HH];
__device__ unsigned g_bar;

__global__ void reset_kernel() { g_bar = 0u; }

// ---------------- helpers ----------------
__device__ __forceinline__ uint32_t s2u(const void* p) {
    uint32_t a;
    asm("{ .reg .u64 t; cvta.to.shared.u64 t, %1; cvt.u32.u64 %0, t; }"
        : "=r"(a) : "l"(p));
    return a;
}

#define LDM4(r, addr) \
    asm volatile("ldmatrix.sync.aligned.m8n8.x4.shared.b16 {%0,%1,%2,%3}, [%4];" \
                 : "=r"((r)[0]), "=r"((r)[1]), "=r"((r)[2]), "=r"((r)[3]) \
                 : "r"(addr))

#define MMA(d, a, b0_, b1_) \
    asm volatile("mma.sync.aligned.m16n8k16.row.col.f32.bf16.bf16.f32 " \
                 "{%0,%1,%2,%3}, {%4,%5,%6,%7}, {%8,%9}, {%0,%1,%2,%3};" \
                 : "+f"((d)[0]), "+f"((d)[1]), "+f"((d)[2]), "+f"((d)[3]) \
                 : "r"((a)[0]), "r"((a)[1]), "r"((a)[2]), "r"((a)[3]), \
                   "r"(b0_), "r"(b1_))

__device__ __forceinline__ void cp16(uint32_t dst, const void* src) {
    asm volatile("cp.async.cg.shared.global [%0], [%1], 16;"
                 :: "r"(dst), "l"(src));
}
__device__ __forceinline__ void cp_commit() {
    asm volatile("cp.async.commit_group;" ::: "memory");
}
__device__ __forceinline__ ushort_t bfu(__nv_bfloat16 v) { return __bfloat16_as_ushort(v); }

// stage chunk ch of h (both planes) into buffer buf
__device__ __forceinline__ void stage_chunk(uint32_t sbA,
                                            const __nv_bfloat16* hhi,
                                            const __nv_bfloat16* hlo,
                                            int ch, int buf, int tid) {
    const uint32_t base = sbA + (uint32_t)buf * A_BUF;
#pragma unroll
    for (int q = 0; q < 8; ++q) {
        int idx = q * NTHR + tid;
        int b  = idx >> 3;
        int k4 = idx & 7;
        int koff = ch * KC + k4 * 8;
        uint32_t dst = base + (uint32_t)(k4 >> 1) * A_KT + (uint32_t)b * 32
                     + (((uint32_t)(k4 & 1) * 16) ^ (((uint32_t)b & 4) << 2));
        cp16(dst,          hhi + (size_t)b * HH + koff);
        cp16(dst + A_VARS, hlo + (size_t)b * HH + koff);
    }
}

// ---------------- main LSTM kernel ----------------
__global__ void __launch_bounds__(NTHR, 1) lstm_kernel(
    const float* __restrict__ x,
    const float* __restrict__ Wgx, const float* __restrict__ Wgh, const float* __restrict__ bg,
    const float* __restrict__ Wix, const float* __restrict__ Wih, const float* __restrict__ bi,
    const float* __restrict__ Wfx, const float* __restrict__ Wfh, const float* __restrict__ bf,
    const float* __restrict__ Wox, const float* __restrict__ Woh, const float* __restrict__ bo)
{
    extern __shared__ char smraw[];
    const uint32_t rawu = s2u(smraw);
    const uint32_t sb = (rawu + 127u) & ~127u;
    char* smem = smraw + (sb - rawu);

    const int tid  = threadIdx.x;
    const int lane = tid & 31;
    const int warp = tid >> 5;
    const int j0   = blockIdx.x * JPC;

    // ---- one-time: W hi/lo -> SMEM ktile layout with (n&4) flip ----
    {
        const float* Wh[4] = {Wgh, Wih, Wfh, Woh};
        for (int idx = tid; idx < 32 * HH; idx += NTHR) {
            int n = idx >> 10, k = idx & (HH - 1);
            float w = Wh[n >> 3][(size_t)(j0 + (n & 7)) * HH + k];
            __nv_bfloat16 hi = __float2bfloat16(w);
            __nv_bfloat16 lo = __float2bfloat16(w - __bfloat162float(hi));
            uint32_t off = (uint32_t)(k >> 4) * 1024u + (uint32_t)n * 32u
                         + (((uint32_t)(k & 15) * 2u) ^ (((uint32_t)n & 4u) << 2));
            *(ushort_t*)(smem + off)         = bfu(hi);
            *(ushort_t*)(smem + W_VAR + off) = bfu(lo);
        }
    }
    float* s_xw = (float*)(smem + SM_XW);
    float* s_bs = (float*)(smem + SM_BS);
    if (tid < 8) {
        s_xw[tid]      = Wgx[j0 + tid];  s_xw[8 + tid]  = Wix[j0 + tid];
        s_xw[16 + tid] = Wfx[j0 + tid];  s_xw[24 + tid] = Wox[j0 + tid];
        s_bs[tid]      = bg[j0 + tid];   s_bs[8 + tid]  = bi[j0 + tid];
        s_bs[16 + tid] = bf[j0 + tid];   s_bs[24 + tid] = bo[j0 + tid];
    }
    __syncthreads();

    // ---- per-lane ldmatrix base addresses ----
    uint32_t aAddr[2][2];   // [mtile][var]
#pragma unroll
    for (int mt = 0; mt < 2; ++mt) {
        int b = warp * 32 + mt * 16 + (lane & 15);
#pragma unroll
        for (int v = 0; v < 2; ++v)
            aAddr[mt][v] = sb + A_BASE + (uint32_t)v * A_VARS + (uint32_t)b * 32
                         + (((uint32_t)(lane >> 4) * 16) ^ (((uint32_t)b & 4) << 2));
    }
    uint32_t bAddr[2][2];   // [ntile-pair][var]
#pragma unroll
    for (int p = 0; p < 2; ++p) {
        int n = p * 16 + ((lane >> 4) << 3) + (lane & 7);
#pragma unroll
        for (int v = 0; v < 2; ++v)
            bAddr[p][v] = sb + (uint32_t)v * W_VAR + (uint32_t)n * 32
                        + (((uint32_t)((lane >> 3) & 1) * 16) ^ (((uint32_t)n & 4) << 2));
    }

    float cst[2][2][2];
#pragma unroll
    for (int a = 0; a < 2; ++a)
#pragma unroll
        for (int bq = 0; bq < 2; ++bq)
            { cst[a][bq][0] = 0.0f; cst[a][bq][1] = 0.0f; }

    const int u0 = (lane & 3) * 2;

    for (int t = 0; t < TT; ++t) {
        float D[2][4][4];
#pragma unroll
        for (int mt = 0; mt < 2; ++mt)
#pragma unroll
            for (int nt = 0; nt < 4; ++nt)
#pragma unroll
                for (int e = 0; e < 4; ++e) D[mt][nt][e] = 0.0f;

        if (t > 0) {
            const __nv_bfloat16* hhi = g_hhi[(t - 1) & 1];
            const __nv_bfloat16* hlo = g_hlo[(t - 1) & 1];
            stage_chunk(sb + A_BASE, hhi, hlo, 0, 0, tid); cp_commit();
            stage_chunk(sb + A_BASE, hhi, hlo, 1, 1, tid); cp_commit();

            for (int ch = 0; ch < NCH; ++ch) {
                if (ch < NCH - 1) asm volatile("cp.async.wait_group 1;" ::: "memory");
                else              asm volatile("cp.async.wait_group 0;" ::: "memory");
                __syncthreads();

                const uint32_t boff = (uint32_t)(ch & 1) * A_BUF;
#pragma unroll
                for (int q = 0; q < 4; ++q) {
                    const uint32_t ao = boff + (uint32_t)q * A_KT;
                    const uint32_t wo = (uint32_t)(ch * 4 + q) * 1024u;
                    uint32_t ah0[4], ah1[4], al0[4], al1[4];
                    uint32_t bh0[4], bh1[4], bl0[4], bl1[4];
                    LDM4(ah0, aAddr[0][0] + ao);
                    LDM4(ah1, aAddr[1][0] + ao);
                    LDM4(al0, aAddr[0][1] + ao);
                    LDM4(al1, aAddr[1][1] + ao);
                    LDM4(bh0, bAddr[0][0] + wo);
                    LDM4(bh1, bAddr[1][0] + wo);
                    LDM4(bl0, bAddr[0][1] + wo);
                    LDM4(bl1, bAddr[1][1] + wo);
                    // pass 1: Ahi * Bhi
                    MMA(D[0][0], ah0, bh0[0], bh0[1]);
                    MMA(D[0][1], ah0, bh0[2], bh0[3]);
                    MMA(D[0][2], ah0, bh1[0], bh1[1]);
                    MMA(D[0][3], ah0, bh1[2], bh1[3]);
                    MMA(D[1][0], ah1, bh0[0], bh0[1]);
                    MMA(D[1][1], ah1, bh0[2], bh0[3]);
                    MMA(D[1][2], ah1, bh1[0], bh1[1]);
                    MMA(D[1][3], ah1, bh1[2], bh1[3]);
                    // pass 2: Ahi * Blo
                    MMA(D[0][0], ah0, bl0[0], bl0[1]);
                    MMA(D[0][1], ah0, bl0[2], bl0[3]);
                    MMA(D[0][2], ah0, bl1[0], bl1[1]);
                    MMA(D[0][3], ah0, bl1[2], bl1[3]);
                    MMA(D[1][0], ah1, bl0[0], bl0[1]);
                    MMA(D[1][1], ah1, bl0[2], bl0[3]);
                    MMA(D[1][2], ah1, bl1[0], bl1[1]);
                    MMA(D[1][3], ah1, bl1[2], bl1[3]);
                    // pass 3: Alo * Bhi
                    MMA(D[0][0], al0, bh0[0], bh0[1]);
                    MMA(D[0][1], al0, bh0[2], bh0[3]);
                    MMA(D[0][2], al0, bh1[0], bh1[1]);
                    MMA(D[0][3], al0, bh1[2], bh1[3]);
                    MMA(D[1][0], al1, bh0[0], bh0[1]);
                    MMA(D[1][1], al1, bh0[2], bh0[3]);
                    MMA(D[1][2], al1, bh1[0], bh1[1]);
                    MMA(D[1][3], al1, bh1[2], bh1[3]);
                }
                __syncthreads();
                if (ch + 2 < NCH) {
                    stage_chunk(sb + A_BASE, hhi, hlo, ch + 2, ch & 1, tid);
                    cp_commit();
                }
            }
        }

        // ---- epilogue: cell update fully in registers ----
        __nv_bfloat16* hhic = g_hhi[t & 1];
        __nv_bfloat16* hloc = g_hlo[t & 1];
#pragma unroll
        for (int mt = 0; mt < 2; ++mt) {
#pragma unroll
            for (int rr = 0; rr < 2; ++rr) {
                const int b = warp * 32 + mt * 16 + rr * 8 + (lane >> 2);
                const float xv = x[b * TT + t];
                ushort_t hh[2], hl[2];
#pragma unroll
                for (int uu = 0; uu < 2; ++uu) {
                    const int u = u0 + uu;
                    const int e = rr * 2 + uu;
                    float zg = D[mt][0][e] + xv * s_xw[u]      + s_bs[u];
                    float zi = D[mt][1][e] + xv * s_xw[8 + u]  + s_bs[8 + u];
                    float zf = D[mt][2][e] + xv * s_xw[16 + u] + s_bs[16 + u];
                    float zo = D[mt][3][e] + xv * s_xw[24 + u] + s_bs[24 + u];
                    float gg = tanhf(zg);
                    float ii = 1.0f / (1.0f + __expf(-zi));
                    float ff = 1.0f / (1.0f + __expf(-zf));
                    float oo = 1.0f / (1.0f + __expf(-zo));
                    float c  = cst[mt][rr][uu];
                    c = gg * ii + c * ff;
                    cst[mt][rr][uu] = c;
                    float hn = tanhf(c) * oo;
                    __nv_bfloat16 hb = __float2bfloat16(hn);
                    __nv_bfloat16 lb = __float2bfloat16(hn - __bfloat162float(hb));
                    hh[uu] = bfu(hb);
                    hl[uu] = bfu(lb);
                }
                uint32_t phi = ((uint32_t)hh[1] << 16) | hh[0];
                uint32_t plo = ((uint32_t)hl[1] << 16) | hl[0];
                *(uint32_t*)&hhic[(size_t)b * HH + j0 + u0] = phi;
                *(uint32_t*)&hloc[(size_t)b * HH + j0 + u0] = plo;
            }
        }

        // ---- grid barrier ----
        __syncthreads();
        if (tid == 0) {
            __threadfence();
            atomicAdd(&g_bar, 1u);
            const unsigned tgt = (unsigned)(t + 1) * NCTA;
            while (*(volatile unsigned*)&g_bar < tgt) { __nanosleep(32); }
            __threadfence();
        }
        __syncthreads();
    }
}

// ---------------- projection ----------------
__global__ void proj_kernel(const float* __restrict__ Wp,
                            const float* __restrict__ bp,
                            float* __restrict__ out)
{
    __shared__ float red[256][CC];
    const int b = blockIdx.x;
    const int tid = threadIdx.x;
    const __nv_bfloat16* hi = g_hhi[(TT - 1) & 1];
    const __nv_bfloat16* lo = g_hlo[(TT - 1) & 1];

    float p[CC];
#pragma unroll
    for (int c = 0; c < CC; ++c) p[c] = 0.0f;
    for (int k = tid; k < HH; k += 256) {
        float hv = __bfloat162float(hi[(size_t)b * HH + k])
                 + __bfloat162float(lo[(size_t)b * HH + k]);
#pragma unroll
        for (int c = 0; c < CC; ++c) p[c] += hv * Wp[k * CC + c];
    }
#pragma unroll
    for (int c = 0; c < CC; ++c) red[tid][c] = p[c];
    __syncthreads();
    if (tid < CC) {
        float s = 0.0f;
        for (int i = 0; i < 256; ++i) s += red[i][tid];
        out[b * CC + tid] = s + bp[tid];
    }
}

extern "C" void kernel_launch(void* const* d_in, const int* in_sizes, int n_in,
                              void* d_out, int out_size)
{
    (void)in_sizes; (void)n_in; (void)out_size;
    const float* x   = (const float*)d_in[0];
    const float* Wgx = (const float*)d_in[1];
    const float* Wgh = (const float*)d_in[2];
    const float* bg  = (const float*)d_in[3];
    const float* Wix = (const float*)d_in[4];
    const float* Wih = (const float*)d_in[5];
    const float* bi  = (const float*)d_in[6];
    const float* Wfx = (const float*)d_in[7];
    const float* Wfh = (const float*)d_in[8];
    const float* bf  = (const float*)d_in[9];
    const float* Wox = (const float*)d_in[10];
    const float* Woh = (const float*)d_in[11];
    const float* bo  = (const float*)d_in[12];
    const float* Wp  = (const float*)d_in[13];
    const float* bp  = (const float*)d_in[14];

    cudaFuncSetAttribute(lstm_kernel,
                         cudaFuncAttributeMaxDynamicSharedMemorySize, SMEM_DYN);

    reset_kernel<<<1, 1>>>();
    lstm_kernel<<<NCTA, NTHR, SMEM_DYN>>>(x, Wgx, Wgh, bg, Wix, Wih, bi,
                                          Wfx, Wfh, bf, Wox, Woh, bo);
    proj_kernel<<<BB, 256>>>(Wp, bp, (float*)d_out);
}

// round 4
// speedup vs baseline: 2.5714x; 1.0175x over previous
#include <cuda_runtime.h>
#include <cuda_bf16.h>
#include <stdint.h>

// LSTM B=128,T=256,H=1024,C=10 — persistent mma.sync(bf16, 3-pass split) kernel.
// R4: 256 threads / 8 warps per CTA (2 warps/SMSP) for latency hiding.

#define BB   128
#define TT   256
#define HH   1024
#define CC   10
#define NCTA 128
#define NTHR 256
#define JPC  8          // hidden units per CTA (32 gate rows)
#define KC   64         // K per staged chunk
#define NCH  16         // chunks per step

// ---- SMEM layout (byte offsets from 128B-aligned base) ----
#define W_VAR   65536
#define A_BASE  131072
#define A_KT    4128          // 128*32 + 32 skew
#define A_VARS  16512         // 4 ktiles
#define A_BUF   33024         // 2 vars
#define MISC    (A_BASE + 2*A_BUF)      // 197120
#define SM_XW   (MISC)
#define SM_BS   (MISC + 128)
#define SMEM_DYN (MISC + 256 + 128)

typedef unsigned short ushort_t;

__device__ __align__(16) __nv_bfloat16 g_hhi[2][BB * HH];  // [b][k]
__device__ __align__(16) __nv_bfloat16 g_hlo[2][BB * HH];
__device__ unsigned g_bar;

__global__ void reset_kernel() { g_bar = 0u; }

// ---------------- helpers ----------------
__device__ __forceinline__ uint32_t s2u(const void* p) {
    uint32_t a;
    asm("{ .reg .u64 t; cvta.to.shared.u64 t, %1; cvt.u32.u64 %0, t; }"
        : "=r"(a) : "l"(p));
    return a;
}

#define LDM4(r, addr) \
    asm volatile("ldmatrix.sync.aligned.m8n8.x4.shared.b16 {%0,%1,%2,%3}, [%4];" \
                 : "=r"((r)[0]), "=r"((r)[1]), "=r"((r)[2]), "=r"((r)[3]) \
                 : "r"(addr))

#define MMA(d, a, b0_, b1_) \
    asm volatile("mma.sync.aligned.m16n8k16.row.col.f32.bf16.bf16.f32 " \
                 "{%0,%1,%2,%3}, {%4,%5,%6,%7}, {%8,%9}, {%0,%1,%2,%3};" \
                 : "+f"((d)[0]), "+f"((d)[1]), "+f"((d)[2]), "+f"((d)[3]) \
                 : "r"((a)[0]), "r"((a)[1]), "r"((a)[2]), "r"((a)[3]), \
                   "r"(b0_), "r"(b1_))

__device__ __forceinline__ void cp16(uint32_t dst, const void* src) {
    asm volatile("cp.async.cg.shared.global [%0], [%1], 16;"
                 :: "r"(dst), "l"(src));
}
__device__ __forceinline__ void cp_commit() {
    asm volatile("cp.async.commit_group;" ::: "memory");
}
__device__ __forceinline__ ushort_t bfu(__nv_bfloat16 v) { return __bfloat16_as_ushort(v); }

// stage chunk ch of h (both planes) into buffer buf
__device__ __forceinline__ void stage_chunk(uint32_t sbA,
                                            const __nv_bfloat16* hhi,
                                            const __nv_bfloat16* hlo,
                                            int ch, int buf, int tid) {
    const uint32_t base = sbA + (uint32_t)buf * A_BUF;
#pragma unroll
    for (int q = 0; q < 4; ++q) {
        int idx = q * NTHR + tid;
        int b  = idx >> 3;
        int k4 = idx & 7;
        int koff = ch * KC + k4 * 8;
        uint32_t dst = base + (uint32_t)(k4 >> 1) * A_KT + (uint32_t)b * 32
                     + (((uint32_t)(k4 & 1) * 16) ^ (((uint32_t)b & 4) << 2));
        cp16(dst,          hhi + (size_t)b * HH + koff);
        cp16(dst + A_VARS, hlo + (size_t)b * HH + koff);
    }
}

// ---------------- main LSTM kernel ----------------
__global__ void __launch_bounds__(NTHR, 1) lstm_kernel(
    const float* __restrict__ x,
    const float* __restrict__ Wgx, const float* __restrict__ Wgh, const float* __restrict__ bg,
    const float* __restrict__ Wix, const float* __restrict__ Wih, const float* __restrict__ bi,
    const float* __restrict__ Wfx, const float* __restrict__ Wfh, const float* __restrict__ bf,
    const float* __restrict__ Wox, const float* __restrict__ Woh, const float* __restrict__ bo)
{
    extern __shared__ char smraw[];
    const uint32_t rawu = s2u(smraw);
    const uint32_t sb = (rawu + 127u) & ~127u;
    char* smem = smraw + (sb - rawu);

    const int tid  = threadIdx.x;
    const int lane = tid & 31;
    const int warp = tid >> 5;
    const int j0   = blockIdx.x * JPC;

    // ---- one-time: W hi/lo -> SMEM ktile layout with (n&4) flip ----
    {
        const float* Wh[4] = {Wgh, Wih, Wfh, Woh};
        for (int idx = tid; idx < 32 * HH; idx += NTHR) {
            int n = idx >> 10, k = idx & (HH - 1);
            float w = Wh[n >> 3][(size_t)(j0 + (n & 7)) * HH + k];
            __nv_bfloat16 hi = __float2bfloat16(w);
            __nv_bfloat16 lo = __float2bfloat16(w - __bfloat162float(hi));
            uint32_t off = (uint32_t)(k >> 4) * 1024u + (uint32_t)n * 32u
                         + (((uint32_t)(k & 15) * 2u) ^ (((uint32_t)n & 4u) << 2));
            *(ushort_t*)(smem + off)         = bfu(hi);
            *(ushort_t*)(smem + W_VAR + off) = bfu(lo);
        }
    }
    float* s_xw = (float*)(smem + SM_XW);
    float* s_bs = (float*)(smem + SM_BS);
    if (tid < 8) {
        s_xw[tid]      = Wgx[j0 + tid];  s_xw[8 + tid]  = Wix[j0 + tid];
        s_xw[16 + tid] = Wfx[j0 + tid];  s_xw[24 + tid] = Wox[j0 + tid];
        s_bs[tid]      = bg[j0 + tid];   s_bs[8 + tid]  = bi[j0 + tid];
        s_bs[16 + tid] = bf[j0 + tid];   s_bs[24 + tid] = bo[j0 + tid];
    }
    __syncthreads();

    // ---- per-lane ldmatrix base addresses ----
    // A: this warp's M=16 tile (batch rows warp*16 .. warp*16+15)
    uint32_t aAddr[2];   // [var]
    {
        int b = warp * 16 + (lane & 15);
#pragma unroll
        for (int v = 0; v < 2; ++v)
            aAddr[v] = sb + A_BASE + (uint32_t)v * A_VARS + (uint32_t)b * 32
                     + (((uint32_t)(lane >> 4) * 16) ^ (((uint32_t)b & 4) << 2));
    }
    uint32_t bAddr[2][2];   // [ntile-pair][var]
#pragma unroll
    for (int p = 0; p < 2; ++p) {
        int n = p * 16 + ((lane >> 4) << 3) + (lane & 7);
#pragma unroll
        for (int v = 0; v < 2; ++v)
            bAddr[p][v] = sb + (uint32_t)v * W_VAR + (uint32_t)n * 32
                        + (((uint32_t)((lane >> 3) & 1) * 16) ^ (((uint32_t)n & 4) << 2));
    }

    float cst[2][2];
#pragma unroll
    for (int rr = 0; rr < 2; ++rr) { cst[rr][0] = 0.0f; cst[rr][1] = 0.0f; }

    const int u0 = (lane & 3) * 2;

    for (int t = 0; t < TT; ++t) {
        float D[4][4];
#pragma unroll
        for (int nt = 0; nt < 4; ++nt)
#pragma unroll
            for (int e = 0; e < 4; ++e) D[nt][e] = 0.0f;

        if (t > 0) {
            const __nv_bfloat16* hhi = g_hhi[(t - 1) & 1];
            const __nv_bfloat16* hlo = g_hlo[(t - 1) & 1];
            stage_chunk(sb + A_BASE, hhi, hlo, 0, 0, tid); cp_commit();
            stage_chunk(sb + A_BASE, hhi, hlo, 1, 1, tid); cp_commit();

            for (int ch = 0; ch < NCH; ++ch) {
                if (ch < NCH - 1) asm volatile("cp.async.wait_group 1;" ::: "memory");
                else              asm volatile("cp.async.wait_group 0;" ::: "memory");
                __syncthreads();

                const uint32_t boff = (uint32_t)(ch & 1) * A_BUF;
#pragma unroll
                for (int q = 0; q < 4; ++q) {
                    const uint32_t ao = boff + (uint32_t)q * A_KT;
                    const uint32_t wo = (uint32_t)(ch * 4 + q) * 1024u;
                    uint32_t ah[4], al[4];
                    uint32_t bh0[4], bh1[4], bl0[4], bl1[4];
                    LDM4(ah, aAddr[0] + ao);
                    LDM4(al, aAddr[1] + ao);
                    LDM4(bh0, bAddr[0][0] + wo);
                    LDM4(bh1, bAddr[1][0] + wo);
                    LDM4(bl0, bAddr[0][1] + wo);
                    LDM4(bl1, bAddr[1][1] + wo);
                    // pass 1: Ahi * Bhi
                    MMA(D[0], ah, bh0[0], bh0[1]);
                    MMA(D[1], ah, bh0[2], bh0[3]);
                    MMA(D[2], ah, bh1[0], bh1[1]);
                    MMA(D[3], ah, bh1[2], bh1[3]);
                    // pass 2: Ahi * Blo
                    MMA(D[0], ah, bl0[0], bl0[1]);
                    MMA(D[1], ah, bl0[2], bl0[3]);
                    MMA(D[2], ah, bl1[0], bl1[1]);
                    MMA(D[3], ah, bl1[2], bl1[3]);
                    // pass 3: Alo * Bhi
                    MMA(D[0], al, bh0[0], bh0[1]);
                    MMA(D[1], al, bh0[2], bh0[3]);
                    MMA(D[2], al, bh1[0], bh1[1]);
                    MMA(D[3], al, bh1[2], bh1[3]);
                }
                __syncthreads();
                if (ch + 2 < NCH) {
                    stage_chunk(sb + A_BASE, hhi, hlo, ch + 2, ch & 1, tid);
                    cp_commit();
                }
            }
        }

        // ---- epilogue: cell update fully in registers ----
        __nv_bfloat16* hhic = g_hhi[t & 1];
        __nv_bfloat16* hloc = g_hlo[t & 1];
#pragma unroll
        for (int rr = 0; rr < 2; ++rr) {
            const int b = warp * 16 + rr * 8 + (lane >> 2);
            const float xv = x[b * TT + t];
            ushort_t hh[2], hl[2];
#pragma unroll
            for (int uu = 0; uu < 2; ++uu) {
                const int u = u0 + uu;
                const int e = rr * 2 + uu;
                float zg = D[0][e] + xv * s_xw[u]      + s_bs[u];
                float zi = D[1][e] + xv * s_xw[8 + u]  + s_bs[8 + u];
                float zf = D[2][e] + xv * s_xw[16 + u] + s_bs[16 + u];
                float zo = D[3][e] + xv * s_xw[24 + u] + s_bs[24 + u];
                float gg = tanhf(zg);
                float ii = 1.0f / (1.0f + __expf(-zi));
                float ff = 1.0f / (1.0f + __expf(-zf));
                float oo = 1.0f / (1.0f + __expf(-zo));
                float c  = cst[rr][uu];
                c = gg * ii + c * ff;
                cst[rr][uu] = c;
                float hn = tanhf(c) * oo;
                __nv_bfloat16 hb = __float2bfloat16(hn);
                __nv_bfloat16 lb = __float2bfloat16(hn - __bfloat162float(hb));
                hh[uu] = bfu(hb);
                hl[uu] = bfu(lb);
            }
            uint32_t phi = ((uint32_t)hh[1] << 16) | hh[0];
            uint32_t plo = ((uint32_t)hl[1] << 16) | hl[0];
            *(uint32_t*)&hhic[(size_t)b * HH + j0 + u0] = phi;
            *(uint32_t*)&hloc[(size_t)b * HH + j0 + u0] = plo;
        }

        // ---- grid barrier ----
        __syncthreads();
        if (tid == 0) {
            __threadfence();
            atomicAdd(&g_bar, 1u);
            const unsigned tgt = (unsigned)(t + 1) * NCTA;
            while (*(volatile unsigned*)&g_bar < tgt) { __nanosleep(32); }
            __threadfence();
        }
        __syncthreads();
    }
}

// ---------------- projection ----------------
__global__ void proj_kernel(const float* __restrict__ Wp,
                            const float* __restrict__ bp,
                            float* __restrict__ out)
{
    __shared__ float red[256][CC];
    const int b = blockIdx.x;
    const int tid = threadIdx.x;
    const __nv_bfloat16* hi = g_hhi[(TT - 1) & 1];
    const __nv_bfloat16* lo = g_hlo[(TT - 1) & 1];

    float p[CC];
#pragma unroll
    for (int c = 0; c < CC; ++c) p[c] = 0.0f;
    for (int k = tid; k < HH; k += 256) {
        float hv = __bfloat162float(hi[(size_t)b * HH + k])
                 + __bfloat162float(lo[(size_t)b * HH + k]);
#pragma unroll
        for (int c = 0; c < CC; ++c) p[c] += hv * Wp[k * CC + c];
    }
#pragma unroll
    for (int c = 0; c < CC; ++c) red[tid][c] = p[c];
    __syncthreads();
    if (tid < CC) {
        float s = 0.0f;
        for (int i = 0; i < 256; ++i) s += red[i][tid];
        out[b * CC + tid] = s + bp[tid];
    }
}

extern "C" void kernel_launch(void* const* d_in, const int* in_sizes, int n_in,
                              void* d_out, int out_size)
{
    (void)in_sizes; (void)n_in; (void)out_size;
    const float* x   = (const float*)d_in[0];
    const float* Wgx = (const float*)d_in[1];
    const float* Wgh = (const float*)d_in[2];
    const float* bg  = (const float*)d_in[3];
    const float* Wix = (const float*)d_in[4];
    const float* Wih = (const float*)d_in[5];
    const float* bi  = (const float*)d_in[6];
    const float* Wfx = (const float*)d_in[7];
    const float* Wfh = (const float*)d_in[8];
    const float* bf  = (const float*)d_in[9];
    const float* Wox = (const float*)d_in[10];
    const float* Woh = (const float*)d_in[11];
    const float* bo  = (const float*)d_in[12];
    const float* Wp  = (const float*)d_in[13];
    const float* bp  = (const float*)d_in[14];

    cudaFuncSetAttribute(lstm_kernel,
                         cudaFuncAttributeMaxDynamicSharedMemorySize, SMEM_DYN);

    reset_kernel<<<1, 1>>>();
    lstm_kernel<<<NCTA, NTHR, SMEM_DYN>>>(x, Wgx, Wgh, bg, Wix, Wih, bi,
                                          Wfx, Wfh, bf, Wox, Woh, bo);
    proj_kernel<<<BB, 256>>>(Wp, bp, (float*)d_out);
}

// round 5
// speedup vs baseline: 4.3381x; 1.6871x over previous
#include <cuda_runtime.h>
#include <cuda_bf16.h>
#include <stdint.h>

// LSTM B=128,T=256,H=1024,C=10 — persistent mma.sync(bf16, 3-pass split).
// R5: h stored k-major+swizzled in global; staged via cp.async.bulk (2 ops/chunk)
// instead of 2048 LDGSTS/chunk. A-fragments via ldmatrix.trans, conflict-free.

#define BB   128
#define TT   256
#define HH   1024
#define CC   10
#define NCTA 128
#define NTHR 256
#define JPC  8          // hidden units per CTA (32 gate rows)
#define KC   64         // K per staged chunk
#define NCH  16         // chunks per step

// ---- SMEM layout (byte offsets from 128B-aligned base) ----
#define W_VAR   65536
#define A_BASE  131072
#define A_PL    16384         // plane stride inside a buffer (64 k-rows * 256B)
#define A_BUF   32768         // one buffer: hi+lo planes
#define MISC    (A_BASE + 2*A_BUF)      // 196608
#define SM_XW   (MISC)
#define SM_BS   (MISC + 128)
#define SM_MB   (MISC + 256)            // two 8B mbarriers
#define SMEM_DYN (MISC + 512)

typedef unsigned short ushort_t;

// h planes, k-major: byte(k,b) = k*256 + (((b>>3)^(k&7))<<4) + ((b&7)<<1)
__device__ __align__(128) __nv_bfloat16 g_hhi[2][HH * BB];
__device__ __align__(128) __nv_bfloat16 g_hlo[2][HH * BB];
__device__ unsigned g_bar;

__global__ void reset_kernel() { g_bar = 0u; }

// ---------------- helpers ----------------
__device__ __forceinline__ uint32_t s2u(const void* p) {
    uint32_t a;
    asm("{ .reg .u64 t; cvta.to.shared.u64 t, %1; cvt.u32.u64 %0, t; }"
        : "=r"(a) : "l"(p));
    return a;
}

#define LDM4(r, addr) \
    asm volatile("ldmatrix.sync.aligned.m8n8.x4.shared.b16 {%0,%1,%2,%3}, [%4];" \
                 : "=r"((r)[0]), "=r"((r)[1]), "=r"((r)[2]), "=r"((r)[3]) \
                 : "r"(addr))

#define LDM4T(r, addr) \
    asm volatile("ldmatrix.sync.aligned.m8n8.x4.trans.shared.b16 {%0,%1,%2,%3}, [%4];" \
                 : "=r"((r)[0]), "=r"((r)[1]), "=r"((r)[2]), "=r"((r)[3]) \
                 : "r"(addr))

#define MMA(d, a, b0_, b1_) \
    asm volatile("mma.sync.aligned.m16n8k16.row.col.f32.bf16.bf16.f32 " \
                 "{%0,%1,%2,%3}, {%4,%5,%6,%7}, {%8,%9}, {%0,%1,%2,%3};" \
                 : "+f"((d)[0]), "+f"((d)[1]), "+f"((d)[2]), "+f"((d)[3]) \
                 : "r"((a)[0]), "r"((a)[1]), "r"((a)[2]), "r"((a)[3]), \
                   "r"(b0_), "r"(b1_))

__device__ __forceinline__ void mbar_init(uint32_t mbar, uint32_t cnt) {
    asm volatile("mbarrier.init.shared.b64 [%0], %1;" :: "r"(mbar), "r"(cnt) : "memory");
}
__device__ __forceinline__ void mbar_expect_tx(uint32_t mbar, uint32_t bytes) {
    asm volatile("mbarrier.arrive.expect_tx.shared.b64 _, [%0], %1;"
                 :: "r"(mbar), "r"(bytes) : "memory");
}
__device__ __forceinline__ void bulk_g2s(uint32_t dst, const void* src,
                                         uint32_t bytes, uint32_t mbar) {
    asm volatile("cp.async.bulk.shared::cluster.global.mbarrier::complete_tx::bytes "
                 "[%0], [%1], %2, [%3];"
                 :: "r"(dst), "l"(src), "r"(bytes), "r"(mbar) : "memory");
}
__device__ __forceinline__ void mbar_wait(uint32_t mbar, uint32_t parity) {
    uint32_t done;
    asm volatile(
        "{\n\t.reg .pred p;\n\t"
        "mbarrier.try_wait.parity.acquire.cta.shared::cta.b64 p, [%1], %2;\n\t"
        "selp.b32 %0, 1, 0, p;\n\t}"
        : "=r"(done) : "r"(mbar), "r"(parity) : "memory");
    if (!done) {
        asm volatile(
            "{\n\t.reg .pred P1;\n\t"
            "WL_%=:\n\t"
            "mbarrier.try_wait.parity.acquire.cta.shared::cta.b64 P1, [%0], %1, 0x989680;\n\t"
            "@P1 bra.uni WD_%=;\n\t"
            "bra.uni WL_%=;\n\t"
            "WD_%=:\n\t}"
            :: "r"(mbar), "r"(parity) : "memory");
    }
}
__device__ __forceinline__ void fence_proxy_async_() {
    asm volatile("fence.proxy.async;" ::: "memory");
}
__device__ __forceinline__ ushort_t bfu(__nv_bfloat16 v) { return __bfloat16_as_ushort(v); }

// ---------------- main LSTM kernel ----------------
__global__ void __launch_bounds__(NTHR, 1) lstm_kernel(
    const float* __restrict__ x,
    const float* __restrict__ Wgx, const float* __restrict__ Wgh, const float* __restrict__ bg,
    const float* __restrict__ Wix, const float* __restrict__ Wih, const float* __restrict__ bi,
    const float* __restrict__ Wfx, const float* __restrict__ Wfh, const float* __restrict__ bf,
    const float* __restrict__ Wox, const float* __restrict__ Woh, const float* __restrict__ bo)
{
    extern __shared__ char smraw[];
    const uint32_t rawu = s2u(smraw);
    const uint32_t sb = (rawu + 127u) & ~127u;
    char* smem = smraw + (sb - rawu);

    const int tid  = threadIdx.x;
    const int lane = tid & 31;
    const int warp = tid >> 5;
    const int j0   = blockIdx.x * JPC;

    // ---- one-time: W hi/lo -> SMEM ktile layout with (n&4) flip ----
    {
        const float* Wh[4] = {Wgh, Wih, Wfh, Woh};
        for (int idx = tid; idx < 32 * HH; idx += NTHR) {
            int n = idx >> 10, k = idx & (HH - 1);
            float w = Wh[n >> 3][(size_t)(j0 + (n & 7)) * HH + k];
            __nv_bfloat16 hi = __float2bfloat16(w);
            __nv_bfloat16 lo = __float2bfloat16(w - __bfloat162float(hi));
            uint32_t off = (uint32_t)(k >> 4) * 1024u + (uint32_t)n * 32u
                         + (((uint32_t)(k & 15) * 2u) ^ (((uint32_t)n & 4u) << 2));
            *(ushort_t*)(smem + off)         = bfu(hi);
            *(ushort_t*)(smem + W_VAR + off) = bfu(lo);
        }
    }
    float* s_xw = (float*)(smem + SM_XW);
    float* s_bs = (float*)(smem + SM_BS);
    if (tid < 8) {
        s_xw[tid]      = Wgx[j0 + tid];  s_xw[8 + tid]  = Wix[j0 + tid];
        s_xw[16 + tid] = Wfx[j0 + tid];  s_xw[24 + tid] = Wox[j0 + tid];
        s_bs[tid]      = bg[j0 + tid];   s_bs[8 + tid]  = bi[j0 + tid];
        s_bs[16 + tid] = bf[j0 + tid];   s_bs[24 + tid] = bo[j0 + tid];
    }
    if (tid == 0) { mbar_init(sb + SM_MB, 1); mbar_init(sb + SM_MB + 8, 1); }
    __syncthreads();

    // ---- A ldmatrix.trans per-lane base address ----
    // tile regs order: (m-lo,k-lo),(m-hi,k-lo),(m-lo,k-hi),(m-hi,k-hi)
    uint32_t aBase;
    {
        uint32_t kkb = (((uint32_t)lane & 16u) >> 1) + ((uint32_t)lane & 7u); // 0..15
        uint32_t bg  = (uint32_t)warp * 2u + (((uint32_t)lane >> 3) & 1u);    // b-granule
        uint32_t sw  = (bg ^ ((uint32_t)lane & 7u)) << 4;
        aBase = sb + A_BASE + kkb * 256u + sw;
    }
    // B (weights) ldmatrix addresses (unchanged)
    uint32_t bAddr[2][2];
#pragma unroll
    for (int p = 0; p < 2; ++p) {
        int n = p * 16 + ((lane >> 4) << 3) + (lane & 7);
#pragma unroll
        for (int v = 0; v < 2; ++v)
            bAddr[p][v] = sb + (uint32_t)v * W_VAR + (uint32_t)n * 32
                        + (((uint32_t)((lane >> 3) & 1) * 16) ^ (((uint32_t)n & 4) << 2));
    }

    float cst[2][2];
#pragma unroll
    for (int rr = 0; rr < 2; ++rr) { cst[rr][0] = 0.0f; cst[rr][1] = 0.0f; }

    const int u0 = (lane & 3) * 2;
    unsigned pha0 = 0, pha1 = 0;

    for (int t = 0; t < TT; ++t) {
        float D[4][4];
#pragma unroll
        for (int nt = 0; nt < 4; ++nt)
#pragma unroll
            for (int e = 0; e < 4; ++e) D[nt][e] = 0.0f;

        if (t > 0) {
            const char* hhi = (const char*)g_hhi[(t - 1) & 1];
            const char* hlo = (const char*)g_hlo[(t - 1) & 1];

            if (tid == 0) {
                fence_proxy_async_();
                mbar_expect_tx(sb + SM_MB, 2 * A_PL);
                bulk_g2s(sb + A_BASE,            hhi,            A_PL, sb + SM_MB);
                bulk_g2s(sb + A_BASE + A_PL,     hlo,            A_PL, sb + SM_MB);
                mbar_expect_tx(sb + SM_MB + 8, 2 * A_PL);
                bulk_g2s(sb + A_BASE + A_BUF,        hhi + A_PL, A_PL, sb + SM_MB + 8);
                bulk_g2s(sb + A_BASE + A_BUF + A_PL, hlo + A_PL, A_PL, sb + SM_MB + 8);
            }

            for (int ch = 0; ch < NCH; ++ch) {
                const int bsel = ch & 1;
                if (bsel == 0) { mbar_wait(sb + SM_MB,     pha0 & 1); ++pha0; }
                else           { mbar_wait(sb + SM_MB + 8, pha1 & 1); ++pha1; }

                const uint32_t boff = (uint32_t)bsel * A_BUF;
#pragma unroll
                for (int q = 0; q < 4; ++q) {
                    const uint32_t ao = aBase + boff + (uint32_t)q * 4096u;
                    const uint32_t wo = (uint32_t)(ch * 4 + q) * 1024u;
                    uint32_t ah[4], al[4];
                    uint32_t bh0[4], bh1[4], bl0[4], bl1[4];
                    LDM4T(ah, ao);
                    LDM4T(al, ao + A_PL);
                    LDM4(bh0, bAddr[0][0] + wo);
                    LDM4(bh1, bAddr[1][0] + wo);
                    LDM4(bl0, bAddr[0][1] + wo);
                    LDM4(bl1, bAddr[1][1] + wo);
                    // pass 1: Ahi * Bhi
                    MMA(D[0], ah, bh0[0], bh0[1]);
                    MMA(D[1], ah, bh0[2], bh0[3]);
                    MMA(D[2], ah, bh1[0], bh1[1]);
                    MMA(D[3], ah, bh1[2], bh1[3]);
                    // pass 2: Ahi * Blo
                    MMA(D[0], ah, bl0[0], bl0[1]);
                    MMA(D[1], ah, bl0[2], bl0[3]);
                    MMA(D[2], ah, bl1[0], bl1[1]);
                    MMA(D[3], ah, bl1[2], bl1[3]);
                    // pass 3: Alo * Bhi
                    MMA(D[0], al, bh0[0], bh0[1]);
                    MMA(D[1], al, bh0[2], bh0[3]);
                    MMA(D[2], al, bh1[0], bh1[1]);
                    MMA(D[3], al, bh1[2], bh1[3]);
                }
                __syncthreads();
                if (tid == 0 && ch + 2 < NCH) {
                    const uint32_t mb = sb + SM_MB + (uint32_t)bsel * 8;
                    mbar_expect_tx(mb, 2 * A_PL);
                    bulk_g2s(sb + A_BASE + boff,        hhi + (ch + 2) * A_PL, A_PL, mb);
                    bulk_g2s(sb + A_BASE + boff + A_PL, hlo + (ch + 2) * A_PL, A_PL, mb);
                }
            }
        }

        // ---- epilogue: cell update fully in registers ----
        char* hhic = (char*)g_hhi[t & 1];
        char* hloc = (char*)g_hlo[t & 1];
#pragma unroll
        for (int rr = 0; rr < 2; ++rr) {
            const int b = warp * 16 + rr * 8 + (lane >> 2);
            const float xv = x[b * TT + t];
#pragma unroll
            for (int uu = 0; uu < 2; ++uu) {
                const int u = u0 + uu;
                const int e = rr * 2 + uu;
                float zg = D[0][e] + xv * s_xw[u]      + s_bs[u];
                float zi = D[1][e] + xv * s_xw[8 + u]  + s_bs[8 + u];
                float zf = D[2][e] + xv * s_xw[16 + u] + s_bs[16 + u];
                float zo = D[3][e] + xv * s_xw[24 + u] + s_bs[24 + u];
                float gg = tanhf(zg);
                float ii = 1.0f / (1.0f + __expf(-zi));
                float ff = 1.0f / (1.0f + __expf(-zf));
                float oo = 1.0f / (1.0f + __expf(-zo));
                float c  = cst[rr][uu];
                c = gg * ii + c * ff;
                cst[rr][uu] = c;
                float hn = tanhf(c) * oo;
                __nv_bfloat16 hb = __float2bfloat16(hn);
                __nv_bfloat16 lb = __float2bfloat16(hn - __bfloat162float(hb));
                // k-major swizzled: byte(k,b) = k*256 + (((b>>3)^(k&7))<<4) + ((b&7)<<1)
                const int kA = j0 + u;
                const size_t off = (size_t)kA * 256
                                 + (size_t)((((unsigned)b >> 3) ^ ((unsigned)u & 7u)) << 4)
                                 + (size_t)(((unsigned)b & 7u) << 1);
                *(ushort_t*)(hhic + off) = bfu(hb);
                *(ushort_t*)(hloc + off) = bfu(lb);
            }
        }

        // ---- grid barrier ----
        __syncthreads();
        if (tid == 0) {
            __threadfence();
            atomicAdd(&g_bar, 1u);
            const unsigned tgt = (unsigned)(t + 1) * NCTA;
            while (*(volatile unsigned*)&g_bar < tgt) { __nanosleep(32); }
            __threadfence();
        }
        __syncthreads();
    }
}

// ---------------- projection ----------------
__global__ void proj_kernel(const float* __restrict__ Wp,
                            const float* __restrict__ bp,
                            float* __restrict__ out)
{
    __shared__ float red[256][CC];
    const int b = blockIdx.x;
    const int tid = threadIdx.x;
    const char* hi = (const char*)g_hhi[(TT - 1) & 1];
    const char* lo = (const char*)g_hlo[(TT - 1) & 1];

    float p[CC];
#pragma unroll
    for (int c = 0; c < CC; ++c) p[c] = 0.0f;
    for (int k = tid; k < HH; k += 256) {
        const size_t off = (size_t)k * 256
                         + (size_t)((((unsigned)b >> 3) ^ ((unsigned)k & 7u)) << 4)
                         + (size_t)(((unsigned)b & 7u) << 1);
        float hv = __bfloat162float(__ushort_as_bfloat16(*(const ushort_t*)(hi + off)))
                 + __bfloat162float(__ushort_as_bfloat16(*(const ushort_t*)(lo + off)));
#pragma unroll
        for (int c = 0; c < CC; ++c) p[c] += hv * Wp[k * CC + c];
    }
#pragma unroll
    for (int c = 0; c < CC; ++c) red[tid][c] = p[c];
    __syncthreads();
    if (tid < CC) {
        float s = 0.0f;
        for (int i = 0; i < 256; ++i) s += red[i][tid];
        out[b * CC + tid] = s + bp[tid];
    }
}

extern "C" void kernel_launch(void* const* d_in, const int* in_sizes, int n_in,
                              void* d_out, int out_size)
{
    (void)in_sizes; (void)n_in; (void)out_size;
    const float* x   = (const float*)d_in[0];
    const float* Wgx = (const float*)d_in[1];
    const float* Wgh = (const float*)d_in[2];
    const float* bg  = (const float*)d_in[3];
    const float* Wix = (const float*)d_in[4];
    const float* Wih = (const float*)d_in[5];
    const float* bi  = (const float*)d_in[6];
    const float* Wfx = (const float*)d_in[7];
    const float* Wfh = (const float*)d_in[8];
    const float* bf  = (const float*)d_in[9];
    const float* Wox = (const float*)d_in[10];
    const float* Woh = (const float*)d_in[11];
    const float* bo  = (const float*)d_in[12];
    const float* Wp  = (const float*)d_in[13];
    const float* bp  = (const float*)d_in[14];

    cudaFuncSetAttribute(lstm_kernel,
                         cudaFuncAttributeMaxDynamicSharedMemorySize, SMEM_DYN);

    reset_kernel<<<1, 1>>>();
    lstm_kernel<<<NCTA, NTHR, SMEM_DYN>>>(x, Wgx, Wgh, bg, Wix, Wih, bi,
                                          Wfx, Wfh, bf, Wox, Woh, bo);
    proj_kernel<<<BB, 256>>>(Wp, bp, (float*)d_out);
}